// round 1
// baseline (speedup 1.0000x reference)
#include <cuda_runtime.h>
#include <cuda_bf16.h>

// Problem constants (match reference_code)
#define N0c 200000
#define N1c 50000
#define N2c 12500
#define N3c 3200
#define E0c 500000
#define E1c 125000
#define E2c 32000
#define DINc 128
#define DHc 256
#define DOUTc 128

// ---------------- scratch (static device globals; no allocations) ----------------
__device__ float g_mean[(size_t)N1c * DHc];   // mean aggregate buffer (reused per layer)
__device__ float g_h1[(size_t)N1c * DHc];     // layer-0 output (50000 x 256)
__device__ float g_h2[(size_t)N2c * DHc];     // layer-1 output (12500 x 256)
__device__ int   g_deg[N1c];
__device__ int   g_off[N1c + 1];
__device__ int   g_cur[N1c];
__device__ int   g_esrc[E0c];

// ---------------- CSR build ----------------
__global__ void zero_deg_kernel(int n) {
    int i = blockIdx.x * blockDim.x + threadIdx.x;
    if (i < n) g_deg[i] = 0;
}

__global__ void hist_kernel(const int* __restrict__ dst, int E) {
    int e = blockIdx.x * blockDim.x + threadIdx.x;
    if (e < E) atomicAdd(&g_deg[dst[e]], 1);
}

// Single-block exclusive scan of g_deg[0..n) -> g_off / g_cur. 1024 threads, shfl warp-scan.
__global__ void scan_kernel(int n, int E) {
    __shared__ int wsum[32];
    __shared__ int carry_s;
    int tid = threadIdx.x, lane = tid & 31, wid = tid >> 5;
    if (tid == 0) carry_s = 0;
    __syncthreads();
    for (int base = 0; base < n; base += 1024) {
        int i = base + tid;
        int v = (i < n) ? g_deg[i] : 0;
        int s = v;
        #pragma unroll
        for (int o = 1; o < 32; o <<= 1) {
            int t = __shfl_up_sync(0xffffffffu, s, o);
            if (lane >= o) s += t;
        }
        if (lane == 31) wsum[wid] = s;
        __syncthreads();
        if (wid == 0) {
            int ws = wsum[lane];
            #pragma unroll
            for (int o = 1; o < 32; o <<= 1) {
                int t = __shfl_up_sync(0xffffffffu, ws, o);
                if (lane >= o) ws += t;
            }
            wsum[lane] = ws;
        }
        __syncthreads();
        int warpoff = (wid == 0) ? 0 : wsum[wid - 1];
        int incl = s + warpoff;
        int excl = incl - v + carry_s;
        if (i < n) { g_off[i] = excl; g_cur[i] = excl; }
        __syncthreads();
        if (tid == 1023) carry_s += incl;   // block total
        __syncthreads();
    }
    if (threadIdx.x == 0) g_off[n] = E;
}

__global__ void bucket_kernel(const int* __restrict__ src, const int* __restrict__ dst, int E) {
    int e = blockIdx.x * blockDim.x + threadIdx.x;
    if (e < E) {
        int p = atomicAdd(&g_cur[dst[e]], 1);
        g_esrc[p] = src[e];
    }
}

// ---------------- aggregation: warp per target node, register accumulation ----------------
template <int D>
__global__ void aggregate_kernel(const float* __restrict__ X, float* __restrict__ mean, int n_tgt) {
    int w = (blockIdx.x * blockDim.x + threadIdx.x) >> 5;
    int lane = threadIdx.x & 31;
    if (w >= n_tgt) return;
    int beg = g_off[w], end = g_off[w + 1];
    float acc[D / 32];
    #pragma unroll
    for (int i = 0; i < D / 32; i++) acc[i] = 0.f;
    for (int e = beg; e < end; e++) {
        const float4* row = (const float4*)(X + (size_t)g_esrc[e] * D);
        #pragma unroll
        for (int i = 0; i < D / 128; i++) {
            float4 v = row[lane + 32 * i];
            acc[4 * i + 0] += v.x;
            acc[4 * i + 1] += v.y;
            acc[4 * i + 2] += v.z;
            acc[4 * i + 3] += v.w;
        }
    }
    float inv = 1.f / (float)max(end - beg, 1);
    float4* mrow = (float4*)(mean + (size_t)w * D);
    #pragma unroll
    for (int i = 0; i < D / 128; i++) {
        float4 o;
        o.x = acc[4 * i + 0] * inv;
        o.y = acc[4 * i + 1] * inv;
        o.z = acc[4 * i + 2] * inv;
        o.w = acc[4 * i + 3] * inv;
        mrow[lane + 32 * i] = o;
    }
}

// ---------------- fused dual-A SGEMM: out = act( mean@Wl^T + Xtgt@Wr^T + b ) ----------------
// BM=BN=128, BK=16, 256 threads, 8x8 per thread. K loop walks 2*D: first D from
// (A0=mean, W=Wl), second D from (A1=Xtgt, W=Wr). D is a multiple of BK so each
// k-tile lies entirely in one half.
__global__ void __launch_bounds__(256) sage_gemm(
    const float* __restrict__ A0, const float* __restrict__ A1,
    const float* __restrict__ Wl, const float* __restrict__ Wr,
    const float* __restrict__ bias, float* __restrict__ out,
    int M, int N, int D, int relu)
{
    const int BM = 128, BN = 128, BK = 16, TM = 8, TN = 8;
    __shared__ float As[BK][BM];
    __shared__ float Bs[BK][BN];

    int tid = threadIdx.x;
    int tx = tid % 16, ty = tid / 16;
    int rowBase = blockIdx.x * BM, colBase = blockIdx.y * BN;

    float acc[TM][TN];
    #pragma unroll
    for (int i = 0; i < TM; i++)
        #pragma unroll
        for (int j = 0; j < TN; j++) acc[i][j] = 0.f;

    int ldRow = tid >> 2;            // 0..63
    int ldK4  = (tid & 3) * 4;       // 0,4,8,12

    for (int kt = 0; kt < 2 * D; kt += BK) {
        const float* A = (kt < D) ? A0 : A1;
        const float* W = (kt < D) ? Wl : Wr;
        int kk = (kt < D) ? kt : (kt - D);

        // A tile (BM x BK), stored transposed As[k][row]
        #pragma unroll
        for (int s = 0; s < 2; s++) {
            int r = ldRow + s * 64;
            int grow = rowBase + r;
            float4 v = make_float4(0.f, 0.f, 0.f, 0.f);
            if (grow < M) v = *(const float4*)(A + (size_t)grow * D + kk + ldK4);
            As[ldK4 + 0][r] = v.x;
            As[ldK4 + 1][r] = v.y;
            As[ldK4 + 2][r] = v.z;
            As[ldK4 + 3][r] = v.w;
        }
        // B tile: W is (N x D) row-major -> Bs[k][col]
        #pragma unroll
        for (int s = 0; s < 2; s++) {
            int c = ldRow + s * 64;
            int gcol = colBase + c;
            float4 v = make_float4(0.f, 0.f, 0.f, 0.f);
            if (gcol < N) v = *(const float4*)(W + (size_t)gcol * D + kk + ldK4);
            Bs[ldK4 + 0][c] = v.x;
            Bs[ldK4 + 1][c] = v.y;
            Bs[ldK4 + 2][c] = v.z;
            Bs[ldK4 + 3][c] = v.w;
        }
        __syncthreads();

        #pragma unroll
        for (int k = 0; k < BK; k++) {
            float a[TM], b[TN];
            #pragma unroll
            for (int u = 0; u < 2; u++) {
                float4 t = *(const float4*)&As[k][ty * TM + 4 * u];
                a[4 * u + 0] = t.x; a[4 * u + 1] = t.y; a[4 * u + 2] = t.z; a[4 * u + 3] = t.w;
            }
            #pragma unroll
            for (int u = 0; u < 2; u++) {
                float4 t = *(const float4*)&Bs[k][tx * TN + 4 * u];
                b[4 * u + 0] = t.x; b[4 * u + 1] = t.y; b[4 * u + 2] = t.z; b[4 * u + 3] = t.w;
            }
            #pragma unroll
            for (int i = 0; i < TM; i++)
                #pragma unroll
                for (int j = 0; j < TN; j++)
                    acc[i][j] += a[i] * b[j];
        }
        __syncthreads();
    }

    // epilogue
    #pragma unroll
    for (int i = 0; i < TM; i++) {
        int grow = rowBase + ty * TM + i;
        if (grow >= M) continue;
        #pragma unroll
        for (int u = 0; u < 2; u++) {
            int gcol = colBase + tx * TN + 4 * u;
            float4 o;
            float* pv = &o.x;
            #pragma unroll
            for (int j = 0; j < 4; j++) {
                float v = acc[i][4 * u + j] + bias[gcol + j];
                if (relu) v = fmaxf(v, 0.f);
                pv[j] = v;
            }
            *(float4*)(out + (size_t)grow * N + gcol) = o;
        }
    }
}

// ---------------- host-side layer driver ----------------
static void run_layer(const float* X, const int* src, const int* dst,
                      int E, int n_tgt, int D,
                      const float* Wl, const float* Wr, const float* b,
                      float* outbuf, int Nout, int relu)
{
    zero_deg_kernel<<<(n_tgt + 255) / 256, 256>>>(n_tgt);
    hist_kernel<<<(E + 255) / 256, 256>>>(dst, E);
    scan_kernel<<<1, 1024>>>(n_tgt, E);
    bucket_kernel<<<(E + 255) / 256, 256>>>(src, dst, E);

    float* mean;
    cudaGetSymbolAddress((void**)&mean, g_mean);

    int aggBlocks = (n_tgt * 32 + 255) / 256;
    if (D == 128)
        aggregate_kernel<128><<<aggBlocks, 256>>>(X, mean, n_tgt);
    else
        aggregate_kernel<256><<<aggBlocks, 256>>>(X, mean, n_tgt);

    dim3 grid((n_tgt + 127) / 128, Nout / 128);
    sage_gemm<<<grid, 256>>>(mean, X, Wl, Wr, b, outbuf, n_tgt, Nout, D, relu);
}

extern "C" void kernel_launch(void* const* d_in, const int* in_sizes, int n_in,
                              void* d_out, int out_size)
{
    const float* x    = (const float*)d_in[0];
    const int*   src0 = (const int*)d_in[1];
    const int*   dst0 = (const int*)d_in[2];
    const int*   src1 = (const int*)d_in[3];
    const int*   dst1 = (const int*)d_in[4];
    const int*   src2 = (const int*)d_in[5];
    const int*   dst2 = (const int*)d_in[6];
    const float* wl0  = (const float*)d_in[7];
    const float* wr0  = (const float*)d_in[8];
    const float* b0   = (const float*)d_in[9];
    const float* wl1  = (const float*)d_in[10];
    const float* wr1  = (const float*)d_in[11];
    const float* b1   = (const float*)d_in[12];
    const float* wl2  = (const float*)d_in[13];
    const float* wr2  = (const float*)d_in[14];
    const float* b2   = (const float*)d_in[15];
    float* out = (float*)d_out;

    float *h1, *h2;
    cudaGetSymbolAddress((void**)&h1, g_h1);
    cudaGetSymbolAddress((void**)&h2, g_h2);

    // Layer 0: x (N0 x 128) -> h1 (N1 x 256), relu
    run_layer(x,  src0, dst0, E0c, N1c, DINc, wl0, wr0, b0, h1, DHc, 1);
    // Layer 1: h1 (N1 x 256) -> h2 (N2 x 256), relu
    run_layer(h1, src1, dst1, E1c, N2c, DHc, wl1, wr1, b1, h2, DHc, 1);
    // Layer 2: h2 (N2 x 256) -> out (N3 x 128), no relu
    run_layer(h2, src2, dst2, E2c, N3c, DHc, wl2, wr2, b2, out, DOUTc, 0);
}

// round 2
// speedup vs baseline: 1.9924x; 1.9924x over previous
#include <cuda_runtime.h>
#include <cuda_bf16.h>
#include <cstdint>

// Problem constants (match reference_code)
#define N0c 200000
#define N1c 50000
#define N2c 12500
#define N3c 3200
#define E0c 500000
#define E1c 125000
#define E2c 32000
#define DINc 128
#define DHc 256
#define DOUTc 128

// ---------------- scratch (static device globals; no allocations) ----------------
__device__ float g_mean[(size_t)N1c * DHc];   // mean aggregate buffer (reused per layer)
__device__ float g_h1[(size_t)N1c * DHc];     // layer-0 output (50000 x 256)
__device__ float g_h2[(size_t)N2c * DHc];     // layer-1 output (12500 x 256)
__device__ int   g_deg[N1c];
__device__ int   g_off[N1c + 1];
__device__ int   g_cur[N1c];
__device__ int   g_esrc[E0c];

// ---------------- CSR build ----------------
__global__ void zero_deg_kernel(int n) {
    int i = blockIdx.x * blockDim.x + threadIdx.x;
    if (i < n) g_deg[i] = 0;
}

__global__ void hist_kernel(const int* __restrict__ dst, int E) {
    int e = blockIdx.x * blockDim.x + threadIdx.x;
    if (e < E) atomicAdd(&g_deg[dst[e]], 1);
}

// Single-block exclusive scan of g_deg[0..n) -> g_off / g_cur. 1024 threads, shfl warp-scan.
__global__ void scan_kernel(int n, int E) {
    __shared__ int wsum[32];
    __shared__ int carry_s;
    int tid = threadIdx.x, lane = tid & 31, wid = tid >> 5;
    if (tid == 0) carry_s = 0;
    __syncthreads();
    for (int base = 0; base < n; base += 1024) {
        int i = base + tid;
        int v = (i < n) ? g_deg[i] : 0;
        int s = v;
        #pragma unroll
        for (int o = 1; o < 32; o <<= 1) {
            int t = __shfl_up_sync(0xffffffffu, s, o);
            if (lane >= o) s += t;
        }
        if (lane == 31) wsum[wid] = s;
        __syncthreads();
        if (wid == 0) {
            int ws = wsum[lane];
            #pragma unroll
            for (int o = 1; o < 32; o <<= 1) {
                int t = __shfl_up_sync(0xffffffffu, ws, o);
                if (lane >= o) ws += t;
            }
            wsum[lane] = ws;
        }
        __syncthreads();
        int warpoff = (wid == 0) ? 0 : wsum[wid - 1];
        int incl = s + warpoff;
        int excl = incl - v + carry_s;
        if (i < n) { g_off[i] = excl; g_cur[i] = excl; }
        __syncthreads();
        if (tid == 1023) carry_s += incl;   // block total
        __syncthreads();
    }
    if (threadIdx.x == 0) g_off[n] = E;
}

__global__ void bucket_kernel(const int* __restrict__ src, const int* __restrict__ dst, int E) {
    int e = blockIdx.x * blockDim.x + threadIdx.x;
    if (e < E) {
        int p = atomicAdd(&g_cur[dst[e]], 1);
        g_esrc[p] = src[e];
    }
}

// ---------------- aggregation: warp per target node, register accumulation ----------------
template <int D>
__global__ void aggregate_kernel(const float* __restrict__ X, float* __restrict__ mean, int n_tgt) {
    int w = (blockIdx.x * blockDim.x + threadIdx.x) >> 5;
    int lane = threadIdx.x & 31;
    if (w >= n_tgt) return;
    int beg = g_off[w], end = g_off[w + 1];
    float acc[D / 32];
    #pragma unroll
    for (int i = 0; i < D / 32; i++) acc[i] = 0.f;
    for (int e = beg; e < end; e++) {
        const float4* row = (const float4*)(X + (size_t)g_esrc[e] * D);
        #pragma unroll
        for (int i = 0; i < D / 128; i++) {
            float4 v = row[lane + 32 * i];
            acc[4 * i + 0] += v.x;
            acc[4 * i + 1] += v.y;
            acc[4 * i + 2] += v.z;
            acc[4 * i + 3] += v.w;
        }
    }
    float inv = 1.f / (float)max(end - beg, 1);
    float4* mrow = (float4*)(mean + (size_t)w * D);
    #pragma unroll
    for (int i = 0; i < D / 128; i++) {
        float4 o;
        o.x = acc[4 * i + 0] * inv;
        o.y = acc[4 * i + 1] * inv;
        o.z = acc[4 * i + 2] * inv;
        o.w = acc[4 * i + 3] * inv;
        mrow[lane + 32 * i] = o;
    }
}

// ---------------- tf32 tensor-core fused dual-A GEMM ----------------
// out = act( mean@Wl^T + Xtgt@Wr^T + b )
// Block tile 128x128, BK=32, 256 threads = 8 warps in 2(m) x 4(n) grid.
// Warp tile 64x32 = 4x4 m16n8k8 tf32 mma fragments, fp32 accumulate.

__device__ __forceinline__ uint32_t f2tf32(float f) {
    uint32_t u;
    asm("cvt.rna.tf32.f32 %0, %1;" : "=r"(u) : "f"(f));
    return u;
}

__global__ void __launch_bounds__(256) sage_gemm_tf32(
    const float* __restrict__ A0, const float* __restrict__ A1,
    const float* __restrict__ Wl, const float* __restrict__ Wr,
    const float* __restrict__ bias, float* __restrict__ out,
    int M, int N, int D, int relu)
{
    const int BM = 128, BK = 32;
    const int LDS_ = BK + 4;  // 36 words -> conflict-free fragment reads
    __shared__ uint32_t As[BM * LDS_];
    __shared__ uint32_t Bs[BM * LDS_];

    int tid = threadIdx.x;
    int lane = tid & 31, wid = tid >> 5;
    int wm = wid & 1;        // 0..1  -> 64-row half
    int wn = wid >> 1;       // 0..3  -> 32-col strip
    int g = lane >> 2, t = lane & 3;

    int rowBase = blockIdx.x * BM, colBase = blockIdx.y * BM;

    float acc[4][4][4];
    #pragma unroll
    for (int i = 0; i < 4; i++)
        #pragma unroll
        for (int j = 0; j < 4; j++)
            #pragma unroll
            for (int r = 0; r < 4; r++) acc[i][j][r] = 0.f;

    int ldr = tid >> 3;          // 0..31 (row within 32-row chunk)
    int ldc = (tid & 7) * 4;     // 0,4,...,28 (k offset)

    for (int kt = 0; kt < 2 * D; kt += BK) {
        const float* A = (kt < D) ? A0 : A1;
        const float* W = (kt < D) ? Wl : Wr;
        int kk = (kt < D) ? kt : (kt - D);

        #pragma unroll
        for (int s = 0; s < 4; s++) {
            int r = ldr + s * 32;
            // A tile (row-guarded)
            int grow = rowBase + r;
            float4 v = make_float4(0.f, 0.f, 0.f, 0.f);
            if (grow < M) v = *(const float4*)(A + (size_t)grow * D + kk + ldc);
            uint4 ua;
            ua.x = f2tf32(v.x); ua.y = f2tf32(v.y); ua.z = f2tf32(v.z); ua.w = f2tf32(v.w);
            *(uint4*)&As[r * LDS_ + ldc] = ua;
            // W tile (N >= colBase+128 always for these shapes)
            float4 w = *(const float4*)(W + (size_t)(colBase + r) * D + kk + ldc);
            uint4 ub;
            ub.x = f2tf32(w.x); ub.y = f2tf32(w.y); ub.z = f2tf32(w.z); ub.w = f2tf32(w.w);
            *(uint4*)&Bs[r * LDS_ + ldc] = ub;
        }
        __syncthreads();

        #pragma unroll
        for (int ks = 0; ks < BK; ks += 8) {
            uint32_t af[4][4];
            #pragma unroll
            for (int mi = 0; mi < 4; mi++) {
                int m = wm * 64 + mi * 16;
                af[mi][0] = As[(m + g)     * LDS_ + ks + t];
                af[mi][1] = As[(m + g + 8) * LDS_ + ks + t];
                af[mi][2] = As[(m + g)     * LDS_ + ks + t + 4];
                af[mi][3] = As[(m + g + 8) * LDS_ + ks + t + 4];
            }
            uint32_t bf[4][2];
            #pragma unroll
            for (int ni = 0; ni < 4; ni++) {
                int n = wn * 32 + ni * 8;
                bf[ni][0] = Bs[(n + g) * LDS_ + ks + t];
                bf[ni][1] = Bs[(n + g) * LDS_ + ks + t + 4];
            }
            #pragma unroll
            for (int mi = 0; mi < 4; mi++)
                #pragma unroll
                for (int ni = 0; ni < 4; ni++) {
                    asm volatile(
                        "mma.sync.aligned.m16n8k8.row.col.f32.tf32.tf32.f32 "
                        "{%0,%1,%2,%3}, {%4,%5,%6,%7}, {%8,%9}, {%0,%1,%2,%3};"
                        : "+f"(acc[mi][ni][0]), "+f"(acc[mi][ni][1]),
                          "+f"(acc[mi][ni][2]), "+f"(acc[mi][ni][3])
                        : "r"(af[mi][0]), "r"(af[mi][1]), "r"(af[mi][2]), "r"(af[mi][3]),
                          "r"(bf[ni][0]), "r"(bf[ni][1]));
                }
        }
        __syncthreads();
    }

    // epilogue: bias + optional relu
    #pragma unroll
    for (int mi = 0; mi < 4; mi++) {
        #pragma unroll
        for (int ni = 0; ni < 4; ni++) {
            int col = colBase + wn * 32 + ni * 8 + t * 2;
            float b0v = bias[col], b1v = bias[col + 1];
            int row0 = rowBase + wm * 64 + mi * 16 + g;
            if (row0 < M) {
                float2 o;
                o.x = acc[mi][ni][0] + b0v;
                o.y = acc[mi][ni][1] + b1v;
                if (relu) { o.x = fmaxf(o.x, 0.f); o.y = fmaxf(o.y, 0.f); }
                *(float2*)(out + (size_t)row0 * N + col) = o;
            }
            int row1 = row0 + 8;
            if (row1 < M) {
                float2 o;
                o.x = acc[mi][ni][2] + b0v;
                o.y = acc[mi][ni][3] + b1v;
                if (relu) { o.x = fmaxf(o.x, 0.f); o.y = fmaxf(o.y, 0.f); }
                *(float2*)(out + (size_t)row1 * N + col) = o;
            }
        }
    }
}

// ---------------- host-side layer driver ----------------
static void run_layer(const float* X, const int* src, const int* dst,
                      int E, int n_tgt, int D,
                      const float* Wl, const float* Wr, const float* b,
                      float* outbuf, int Nout, int relu)
{
    zero_deg_kernel<<<(n_tgt + 255) / 256, 256>>>(n_tgt);
    hist_kernel<<<(E + 255) / 256, 256>>>(dst, E);
    scan_kernel<<<1, 1024>>>(n_tgt, E);
    bucket_kernel<<<(E + 255) / 256, 256>>>(src, dst, E);

    float* mean;
    cudaGetSymbolAddress((void**)&mean, g_mean);

    int aggBlocks = (n_tgt * 32 + 255) / 256;
    if (D == 128)
        aggregate_kernel<128><<<aggBlocks, 256>>>(X, mean, n_tgt);
    else
        aggregate_kernel<256><<<aggBlocks, 256>>>(X, mean, n_tgt);

    dim3 grid((n_tgt + 127) / 128, Nout / 128);
    sage_gemm_tf32<<<grid, 256>>>(mean, X, Wl, Wr, b, outbuf, n_tgt, Nout, D, relu);
}

extern "C" void kernel_launch(void* const* d_in, const int* in_sizes, int n_in,
                              void* d_out, int out_size)
{
    const float* x    = (const float*)d_in[0];
    const int*   src0 = (const int*)d_in[1];
    const int*   dst0 = (const int*)d_in[2];
    const int*   src1 = (const int*)d_in[3];
    const int*   dst1 = (const int*)d_in[4];
    const int*   src2 = (const int*)d_in[5];
    const int*   dst2 = (const int*)d_in[6];
    const float* wl0  = (const float*)d_in[7];
    const float* wr0  = (const float*)d_in[8];
    const float* b0   = (const float*)d_in[9];
    const float* wl1  = (const float*)d_in[10];
    const float* wr1  = (const float*)d_in[11];
    const float* b1   = (const float*)d_in[12];
    const float* wl2  = (const float*)d_in[13];
    const float* wr2  = (const float*)d_in[14];
    const float* b2   = (const float*)d_in[15];
    float* out = (float*)d_out;

    float *h1, *h2;
    cudaGetSymbolAddress((void**)&h1, g_h1);
    cudaGetSymbolAddress((void**)&h2, g_h2);

    // Layer 0: x (N0 x 128) -> h1 (N1 x 256), relu
    run_layer(x,  src0, dst0, E0c, N1c, DINc, wl0, wr0, b0, h1, DHc, 1);
    // Layer 1: h1 (N1 x 256) -> h2 (N2 x 256), relu
    run_layer(h1, src1, dst1, E1c, N2c, DHc, wl1, wr1, b1, h2, DHc, 1);
    // Layer 2: h2 (N2 x 256) -> out (N3 x 128), no relu
    run_layer(h2, src2, dst2, E2c, N3c, DHc, wl2, wr2, b2, out, DOUTc, 0);
}